// round 11
// baseline (speedup 1.0000x reference)
#include <cuda_runtime.h>
#include <cuda_fp16.h>
#include <cstdint>

#define NB     16
#define SEQ    512
#define DMODEL 512
#define MAXF   2048

// scales for fp8 cross-term packing:  cross = [q(xh)q(wl*2^20) + q(xl*2^14)q(wh*2^6)] / 2^20
#define S_XL   16384.0f      // 2^14
#define S_WL   1048576.0f    // 2^20
#define S_WH   64.0f         // 2^6
#define INV_CROSS (1.0f / 1048576.0f)

// ---------------- scratch (static __device__ arrays: allowed) ----------------
// per row: fp16 hi (512*2B) + fp8 pack (8 chunks x 128B = [q(xh) 64 | q(xl*2^14) 64])
__device__ __align__(128) __half  g_Xh [NB * MAXF * DMODEL];   // Hexp hi
__device__ __align__(128) uint8_t g_X8 [NB * MAXF * 1024];     // Hexp fp8 pack
__device__ __align__(128) __half  g_Xdh[NB * SEQ  * DMODEL];   // H hi (dp input)
__device__ __align__(128) uint8_t g_Xd8[NB * SEQ  * 1024];
__device__ __align__(128) __half  g_Yph[NB * MAXF * DMODEL];   // pp layer1 out
__device__ __align__(128) uint8_t g_Yp8[NB * MAXF * 1024];
__device__ __align__(128) __half  g_Yeh[NB * MAXF * DMODEL];   // ep layer1 out
__device__ __align__(128) uint8_t g_Ye8[NB * MAXF * 1024];
__device__ __align__(128) __half  g_Ydh[NB * SEQ  * DMODEL];   // dp layer1 out
__device__ __align__(128) uint8_t g_Yd8[NB * SEQ  * 1024];
// weights: hi fp16 [conv][tap][f][c]; fp8 pack [conv][tap][f][chunk][ q(wl*2^20) 64 | q(wh*2^6) 64 ]
__device__ __align__(128) __half  g_Wh[6 * 3 * 512 * 512];
__device__ __align__(128) uint8_t g_W8[6 * 3 * 512 * 1024];
#define TOTROWS (2 * NB * MAXF + NB * SEQ)   // pp | ep | dp
__device__ float g_part[TOTROWS * 4];
__device__ int   g_idx [NB * MAXF];

// ================= baseline-ISA helpers (compute_103-safe) =================
__device__ __forceinline__ uint32_t smem_to_u32(const void* p) {
    uint32_t a;
    asm("{ .reg .u64 t; cvta.to.shared.u64 t, %1; cvt.u32.u64 %0, t; }" : "=r"(a) : "l"(p));
    return a;
}
__device__ __forceinline__ void cpasync16(uint32_t dst, const void* src, bool pred) {
    int sz = pred ? 16 : 0;
    asm volatile("cp.async.cg.shared.global [%0], [%1], 16, %2;"
                 :: "r"(dst), "l"(src), "r"(sz));
}
#define CP_COMMIT() asm volatile("cp.async.commit_group;" ::: "memory")
#define CP_WAIT1()  asm volatile("cp.async.wait_group 1;"  ::: "memory")

__device__ __forceinline__ void ldmx4(uint32_t* r, uint32_t addr) {
    asm volatile("ldmatrix.sync.aligned.m8n8.x4.shared.b16 {%0,%1,%2,%3}, [%4];"
                 : "=r"(r[0]), "=r"(r[1]), "=r"(r[2]), "=r"(r[3]) : "r"(addr));
}
// fp16 MMA, fp32 accumulate
__device__ __forceinline__ void mma_f16(float* d, const uint32_t* a, const uint32_t* b) {
    asm volatile("mma.sync.aligned.m16n8k16.row.col.f32.f16.f16.f32 "
                 "{%0,%1,%2,%3}, {%4,%5,%6,%7}, {%8,%9}, {%0,%1,%2,%3};"
                 : "+f"(d[0]), "+f"(d[1]), "+f"(d[2]), "+f"(d[3])
                 : "r"(a[0]), "r"(a[1]), "r"(a[2]), "r"(a[3]), "r"(b[0]), "r"(b[1]));
}
// fp8 e4m3 MMA k32, fp32 accumulate — byte-identical fragment layout to fp16 k16
__device__ __forceinline__ void mma_e4m3(float* d, const uint32_t* a, const uint32_t* b) {
    asm volatile("mma.sync.aligned.m16n8k32.row.col.f32.e4m3.e4m3.f32 "
                 "{%0,%1,%2,%3}, {%4,%5,%6,%7}, {%8,%9}, {%0,%1,%2,%3};"
                 : "+f"(d[0]), "+f"(d[1]), "+f"(d[2]), "+f"(d[3])
                 : "r"(a[0]), "r"(a[1]), "r"(a[2]), "r"(a[3]), "r"(b[0]), "r"(b[1]));
}
// single e4m3 quantize (satfinite) — byte-order-independent
__device__ __forceinline__ uint8_t q8(float x) {
    uint16_t t;
    asm("cvt.rn.satfinite.e4m3x2.f32 %0, %1, %1;" : "=h"(t) : "f"(x));
    return (uint8_t)(t & 0xFF);
}
// smem tile offset: row r, 16B segment s (0..7), XOR swizzle
__device__ __forceinline__ uint32_t toff(int r, int s) {
    return (uint32_t)(r * 128 + ((s ^ (r & 7)) << 4));
}

// ---------------- merged weight split (all 6 convs): w[f][c][k] -> Wh/W8 ----------------
__global__ void wsplit_all_kernel(const float* __restrict__ w0, const float* __restrict__ w1,
                                  const float* __restrict__ w2, const float* __restrict__ w3,
                                  const float* __restrict__ w4, const float* __restrict__ w5) {
    int conv = blockIdx.y;
    const float* w = conv == 0 ? w0 : conv == 1 ? w1 : conv == 2 ? w2 :
                     conv == 3 ? w3 : conv == 4 ? w4 : w5;
    int tf  = blockIdx.x;            // tap*512 + f
    int tap = tf >> 9;
    int f   = tf & 511;
    int c   = threadIdx.x;
    float v = w[(f * 512 + c) * 3 + tap];
    __half h = __float2half_rn(v);
    float hf = __half2float(h);
    float rem = v - hf;
    long fo = (long)(conv * 3 + tap) * 512 + f;
    g_Wh[fo * 512 + c] = h;
    long b8 = fo * 1024 + (long)(c >> 6) * 128 + (c & 63);
    g_W8[b8]      = q8(rem * S_WL);
    g_W8[b8 + 64] = q8(hf * S_WH);
}

// ---------------- split fp32 row data -> (fp16 hi, fp8 pack) ----------------
__device__ __forceinline__ void split_store4(__half* Xh, uint8_t* X8, long row, int d,
                                             float4 v) {
    float vv[4] = {v.x, v.y, v.z, v.w};
    __half hh[4];
    float rr[4];
#pragma unroll
    for (int k = 0; k < 4; k++) {
        hh[k] = __float2half_rn(vv[k]);
        rr[k] = vv[k] - __half2float(hh[k]);
    }
    __half2 p01 = __halves2half2(hh[0], hh[1]);
    __half2 p23 = __halves2half2(hh[2], hh[3]);
    long xo = row * 512 + d;
    *(uint32_t*)&Xh[xo]     = *(uint32_t*)&p01;
    *(uint32_t*)&Xh[xo + 2] = *(uint32_t*)&p23;
    uint8_t* base = X8 + row * 1024 + (long)(d >> 6) * 128 + (d & 63);
#pragma unroll
    for (int k = 0; k < 4; k++) {
        base[k]      = q8(__half2float(hh[k]));
        base[64 + k] = q8(rr[k] * S_XL);
    }
}

__global__ void hsplit_kernel(const float* __restrict__ H) {
    long row = blockIdx.x;
    int d = threadIdx.x * 4;
    float4 v = *(const float4*)&H[row * 512 + d];
    split_store4(g_Xdh, g_Xd8, row, d, v);
}

// ---------------- duration cumsum + searchsorted ----------------
__global__ void duration_idx_kernel(const int* __restrict__ Dgt) {
    __shared__ int cs[512];
    int b = blockIdx.x, tid = threadIdx.x;
    int v = Dgt[b * 512 + tid];
    cs[tid] = v > 0 ? v : 0;
    __syncthreads();
    for (int off = 1; off < 512; off <<= 1) {
        int add = (tid >= off) ? cs[tid - off] : 0;
        __syncthreads();
        cs[tid] += add;
        __syncthreads();
    }
    int total = cs[511];
    int Tmax  = total < MAXF ? total : MAXF;
    for (int t = tid; t < MAXF; t += 512) {
        int r;
        if (t >= Tmax) {
            r = -1;
        } else {
            int lo = 0, hi = 511;
            while (lo < hi) {
                int mid = (lo + hi) >> 1;
                if (cs[mid] > t) hi = mid; else lo = mid + 1;
            }
            r = lo;
        }
        g_idx[b * MAXF + t] = r;
    }
}

// ---------------- gather H_exp (split) + fused variance adapt ----------------
__global__ void gather_adapt_kernel(const float* __restrict__ H,
                                    const float* __restrict__ P,
                                    const float* __restrict__ E,
                                    const float* __restrict__ pw,
                                    const float* __restrict__ pb,
                                    const float* __restrict__ ew,
                                    const float* __restrict__ eb,
                                    float* __restrict__ outH) {
    int bt  = blockIdx.x;
    int b   = bt >> 11;
    int idx = g_idx[bt];
    int d   = threadIdx.x * 4;
    float4 h = make_float4(0.f, 0.f, 0.f, 0.f);
    if (idx >= 0) h = *(const float4*)&H[((long)(b * 512 + idx)) * 512 + d];

    split_store4(g_Xh, g_X8, bt, d, h);

    float p = P[bt], e = E[bt];
    float4 pw4 = *(const float4*)&pw[d];
    float4 pb4 = *(const float4*)&pb[d];
    float4 ew4 = *(const float4*)&ew[d];
    float4 eb4 = *(const float4*)&eb[d];
    float4 o;
    o.x = h.x + p * pw4.x + pb4.x + e * ew4.x + eb4.x;
    o.y = h.y + p * pw4.y + pb4.y + e * ew4.y + eb4.y;
    o.z = h.z + p * pw4.z + pb4.z + e * ew4.z + eb4.z;
    o.w = h.w + p * pw4.w + pb4.w + e * ew4.w + eb4.w;
    *(float4*)&outH[(long)bt * 512 + d] = o;
}

// ---------------- conv1d: fp16 main MMA + fp8 packed-cross MMA ----------------
// CTA: 128 rows x 128 filters, 512 threads (16 warps 4Mx4N, warp 32x32).
// 24 iterations = 8 x 64-ch chunks x 3 taps. A double-buffered (130-row halo, taps via
// row offset), B triple-buffered ring (slot == tap). One barrier / iteration.
// smem: A: 2 x (Ah 16640 + A8 16640) | B: 3 x (Bh 16384 + B8 16384)
#define A_HALF  16640
#define A_BUF   (2 * A_HALF)
#define B_BASE  (2 * A_BUF)          // 66560
#define B_HALF  16384
#define B_SLOT  (2 * B_HALF)
#define DSM_TOT (B_BASE + 3 * B_SLOT)   // 164864

template <int FUSED>
__global__ __launch_bounds__(512, 1)
void conv_mma_kernel(int xsel, int conv, int S, long rowOff,
                     const float* __restrict__ bias, const float* __restrict__ wl) {
    extern __shared__ char sm[];
    const uint32_t sb = smem_to_u32(sm);
    __shared__ float s_bias[128];
    __shared__ float s_wl[128];
    __shared__ float s_part[128][4];

    const int tid  = threadIdx.x;
    const int lane = tid & 31;
    const int wid  = tid >> 5;
    const int warpM = wid & 3, warpN = wid >> 2;
    const int rowW = warpM * 32, colW = warpN * 32;

    // input select: 0=Hexp, 1=H(dp), 2=Yp, 3=Ye, 4=Yd ; layer-1 output select
    const __half*  Xh = xsel == 0 ? g_Xh : xsel == 1 ? g_Xdh :
                        xsel == 2 ? g_Yph : xsel == 3 ? g_Yeh : g_Ydh;
    const uint8_t* X8 = xsel == 0 ? g_X8 : xsel == 1 ? g_Xd8 :
                        xsel == 2 ? g_Yp8 : xsel == 3 ? g_Ye8 : g_Yd8;
    __half*  Oh = conv == 2 ? g_Yph : conv == 4 ? g_Yeh : g_Ydh;
    uint8_t* O8 = conv == 2 ? g_Yp8 : conv == 4 ? g_Ye8 : g_Yd8;

    const int rowBase = blockIdx.y * 128;
    const int fBase   = blockIdx.x * 128;
    const int bb = rowBase / S;
    const int s0 = rowBase - bb * S;
    const __half*  Xbh = Xh + (long)bb * S * 512;
    const uint8_t* Xb8 = X8 + (long)bb * S * 1024;
    const __half*  WhC = g_Wh + ((long)(conv * 3) * 512 + fBase) * 512;
    const uint8_t* W8C = g_W8 + ((long)(conv * 3) * 512 + fBase) * 1024;

    if (tid < 128) {
        s_bias[tid] = bias[fBase + tid];
        if (FUSED) s_wl[tid] = wl[fBase + tid];
    }

    // ---- stage A chunk c (64 ch, 130 rows incl halo): fp16 hi + fp8 pack ----
    auto stageA = [&](int c) {
        const int c0 = c << 6;
        const uint32_t abuf = sb + (c & 1) * A_BUF;
#pragma unroll
        for (int q = 0; q < 3; q++) {
            int idx = tid + q * 512;
            if (idx < 1040) {                 // 130 rows x 8 segs
                int r = idx >> 3, s = idx & 7;
                int sr = s0 - 1 + r;
                bool p = (sr >= 0 && sr < S);
                int sc = p ? sr : 0;
                uint32_t a = toff(r, s);
                cpasync16(abuf + a,          Xbh + (long)sc * 512 + c0 + s * 8, p);
                cpasync16(abuf + A_HALF + a, Xb8 + (long)sc * 1024 + c * 128 + s * 16, p);
            }
        }
    };
    // ---- stage B for iteration it (chunk it/3, tap it%3) into slot it%3 ----
    auto stageB = [&](int it) {
        const int tap = it % 3;
        const int c   = it / 3;
        const uint32_t bbuf = sb + B_BASE + tap * B_SLOT;
        const __half*  Wh = WhC + (long)tap * 512 * 512 + (c << 6);
        const uint8_t* W8 = W8C + (long)tap * 512 * 1024 + c * 128;
#pragma unroll
        for (int q = 0; q < 2; q++) {
            int idx = tid + q * 512;          // 128 filters x 8 segs
            int r = idx >> 3, s = idx & 7;
            uint32_t a = toff(r, s);
            cpasync16(bbuf + a,          Wh + (long)r * 512 + s * 8, true);
            cpasync16(bbuf + B_HALF + a, W8 + (long)r * 1024 + s * 16, true);
        }
    };

    // ---- per-lane ldmatrix bases ----
    const int q = lane >> 3;
    int am[2], an[2];
#pragma unroll
    for (int mt = 0; mt < 2; mt++) am[mt] = rowW + mt * 16 + ((q & 1) << 3) + (lane & 7);
#pragma unroll
    for (int np = 0; np < 2; np++) an[np] = colW + np * 16 + ((q >> 1) << 3) + (lane & 7);
    const int ac16b = q >> 1;
    const int bc16b = q & 1;

    float acc [2][4][4];   // fp16 main term
    float acc8[2][4][4];   // fp8 packed cross term (scale 2^20)
#pragma unroll
    for (int mt = 0; mt < 2; mt++)
#pragma unroll
        for (int nt = 0; nt < 4; nt++)
#pragma unroll
            for (int v = 0; v < 4; v++) { acc[mt][nt][v] = 0.f; acc8[mt][nt][v] = 0.f; }

    stageA(0); stageB(0); CP_COMMIT();
    stageB(1);            CP_COMMIT();

    for (int it = 0; it < 24; it++) {
        CP_WAIT1();
        __syncthreads();
        const int tap = it % 3;
        const uint32_t aH = sb + ((it / 3) & 1) * A_BUF;
        const uint32_t a8 = aH + A_HALF;
        const uint32_t bH = sb + B_BASE + tap * B_SLOT;
        const uint32_t b8 = bH + B_HALF;

        // ---- fp16 sub-loop: xh * wh ----
#pragma unroll
        for (int ks = 0; ks < 4; ks++) {
            const int ks2 = ks * 2;
            uint32_t bf[4][2];
#pragma unroll
            for (int np = 0; np < 2; np++) {
                uint32_t t[4];
                ldmx4(t, bH + toff(an[np], ks2 + bc16b));
                bf[2 * np][0] = t[0]; bf[2 * np][1] = t[1];
                bf[2 * np + 1][0] = t[2]; bf[2 * np + 1][1] = t[3];
            }
#pragma unroll
            for (int mt = 0; mt < 2; mt++) {
                const int pr = am[mt] + tap;
                uint32_t af[4];
                ldmx4(af, aH + toff(pr, ks2 + ac16b));
#pragma unroll
                for (int nt = 0; nt < 4; nt++) mma_f16(acc[mt][nt], af, bf[nt]);
            }
        }
        // ---- fp8 sub-loop: packed [xh|xl*2^14] x [wl*2^20|wh*2^6] ----
#pragma unroll
        for (int ks = 0; ks < 4; ks++) {
            const int ks2 = ks * 2;
            uint32_t bf[4][2];
#pragma unroll
            for (int np = 0; np < 2; np++) {
                uint32_t t[4];
                ldmx4(t, b8 + toff(an[np], ks2 + bc16b));
                bf[2 * np][0] = t[0]; bf[2 * np][1] = t[1];
                bf[2 * np + 1][0] = t[2]; bf[2 * np + 1][1] = t[3];
            }
#pragma unroll
            for (int mt = 0; mt < 2; mt++) {
                const int pr = am[mt] + tap;
                uint32_t af[4];
                ldmx4(af, a8 + toff(pr, ks2 + ac16b));
#pragma unroll
                for (int nt = 0; nt < 4; nt++) mma_e4m3(acc8[mt][nt], af, bf[nt]);
            }
        }

        const int nx = it + 2;
        if (nx < 24) {
            if (nx % 3 == 0) stageA(nx / 3);
            stageB(nx);
        }
        CP_COMMIT();
    }

    // ---------------- epilogue ----------------
    const int tq = lane >> 2;
    const int tr = lane & 3;
    if (FUSED == 0) {
#pragma unroll
        for (int mt = 0; mt < 2; mt++) {
            const long r0 = rowBase + rowW + mt * 16 + tq;
#pragma unroll
            for (int nt = 0; nt < 4; nt++) {
                const int cl = colW + nt * 8 + 2 * tr;
                const float b0 = s_bias[cl], b1 = s_bias[cl + 1];
#pragma unroll
                for (int h = 0; h < 2; h++) {
                    const long row = r0 + h * 8;
                    float v0 = fmaxf(acc[mt][nt][2 * h]     + acc8[mt][nt][2 * h]     * INV_CROSS + b0, 0.f);
                    float v1 = fmaxf(acc[mt][nt][2 * h + 1] + acc8[mt][nt][2 * h + 1] * INV_CROSS + b1, 0.f);
                    __half h0 = __float2half_rn(v0);
                    __half h1 = __float2half_rn(v1);
                    float r0f = v0 - __half2float(h0);
                    float r1f = v1 - __half2float(h1);
                    const int C = fBase + cl;
                    __half2 hp = __halves2half2(h0, h1);
                    *(uint32_t*)&Oh[row * 512 + C] = *(uint32_t*)&hp;
                    uint8_t* base = O8 + row * 1024 + (long)(C >> 6) * 128 + (C & 63);
                    base[0]  = q8(__half2float(h0));
                    base[1]  = q8(__half2float(h1));
                    base[64] = q8(r0f * S_XL);
                    base[65] = q8(r1f * S_XL);
                }
            }
        }
    } else {
#pragma unroll
        for (int mt = 0; mt < 2; mt++) {
            float sum0 = 0.f, sum1 = 0.f;
#pragma unroll
            for (int nt = 0; nt < 4; nt++) {
                const int cl = colW + nt * 8 + 2 * tr;
                const float b0 = s_bias[cl], b1 = s_bias[cl + 1];
                const float w0 = s_wl[cl], w1 = s_wl[cl + 1];
                sum0 += fmaxf(acc[mt][nt][0] + acc8[mt][nt][0] * INV_CROSS + b0, 0.f) * w0
                      + fmaxf(acc[mt][nt][1] + acc8[mt][nt][1] * INV_CROSS + b1, 0.f) * w1;
                sum1 += fmaxf(acc[mt][nt][2] + acc8[mt][nt][2] * INV_CROSS + b0, 0.f) * w0
                      + fmaxf(acc[mt][nt][3] + acc8[mt][nt][3] * INV_CROSS + b1, 0.f) * w1;
            }
            sum0 += __shfl_xor_sync(0xFFFFFFFF, sum0, 1);
            sum0 += __shfl_xor_sync(0xFFFFFFFF, sum0, 2);
            sum1 += __shfl_xor_sync(0xFFFFFFFF, sum1, 1);
            sum1 += __shfl_xor_sync(0xFFFFFFFF, sum1, 2);
            if (tr == 0) {
                s_part[rowW + mt * 16 + tq][warpN]     = sum0;
                s_part[rowW + mt * 16 + tq + 8][warpN] = sum1;
            }
        }
        __syncthreads();
        if (tid < 128)
            g_part[(rowOff + rowBase + tid) * 4 + blockIdx.x] =
                (s_part[tid][0] + s_part[tid][1]) + (s_part[tid][2] + s_part[tid][3]);
    }
}

// ---------------- merged final reduce: pp | ep | dp ----------------
__global__ void reduce_all_kernel(const float* __restrict__ pp_bl,
                                  const float* __restrict__ ep_bl,
                                  const float* __restrict__ dp_bl,
                                  float* __restrict__ outP,
                                  float* __restrict__ outE,
                                  float* __restrict__ outD) {
    int i = blockIdx.x * 256 + threadIdx.x;
    if (i >= TOTROWS) return;
    float s = (g_part[(long)i * 4 + 0] + g_part[(long)i * 4 + 1]) +
              (g_part[(long)i * 4 + 2] + g_part[(long)i * 4 + 3]);
    const int nPP = NB * MAXF, nPE = 2 * NB * MAXF;
    if (i < nPP)       outP[i]        = pp_bl[0] + s;
    else if (i < nPE)  outE[i - nPP]  = ep_bl[0] + s;
    else               outD[i - nPE]  = dp_bl[0] + s;
}

// ---------------- launch ----------------
extern "C" void kernel_launch(void* const* d_in, const int* in_sizes, int n_in,
                              void* d_out, int out_size) {
    const float* H     = (const float*)d_in[0];
    const int*   Dgt   = (const int*)  d_in[1];
    const float* Pgt   = (const float*)d_in[2];
    const float* Egt   = (const float*)d_in[3];
    const float* dp_w1 = (const float*)d_in[4];
    const float* dp_b1 = (const float*)d_in[5];
    const float* dp_w2 = (const float*)d_in[6];
    const float* dp_b2 = (const float*)d_in[7];
    const float* dp_wl = (const float*)d_in[8];
    const float* dp_bl = (const float*)d_in[9];
    const float* pp_w1 = (const float*)d_in[10];
    const float* pp_b1 = (const float*)d_in[11];
    const float* pp_w2 = (const float*)d_in[12];
    const float* pp_b2 = (const float*)d_in[13];
    const float* pp_wl = (const float*)d_in[14];
    const float* pp_bl = (const float*)d_in[15];
    const float* ep_w1 = (const float*)d_in[16];
    const float* ep_b1 = (const float*)d_in[17];
    const float* ep_w2 = (const float*)d_in[18];
    const float* ep_b2 = (const float*)d_in[19];
    const float* ep_wl = (const float*)d_in[20];
    const float* ep_bl = (const float*)d_in[21];
    const float* pw    = (const float*)d_in[22];
    const float* pb    = (const float*)d_in[23];
    const float* ew    = (const float*)d_in[24];
    const float* eb    = (const float*)d_in[25];

    float* out  = (float*)d_out;
    float* outH = out;                                   // (16,2048,512)
    float* outD = out + (long)NB * MAXF * DMODEL;        // (16,512)
    float* outP = outD + NB * SEQ;                       // (16,2048)
    float* outE = outP + NB * MAXF;                      // (16,2048)

    cudaFuncSetAttribute(conv_mma_kernel<0>, cudaFuncAttributeMaxDynamicSharedMemorySize, DSM_TOT);
    cudaFuncSetAttribute(conv_mma_kernel<1>, cudaFuncAttributeMaxDynamicSharedMemorySize, DSM_TOT);

    const long OFF_PP = 0, OFF_EP = (long)NB * MAXF, OFF_DP = 2L * NB * MAXF;

    // 1: weight splits (all 6 convs)
    wsplit_all_kernel<<<dim3(1536, 6), 512>>>(dp_w1, dp_w2, pp_w1, pp_w2, ep_w1, ep_w2);
    // 2: duration indices
    duration_idx_kernel<<<NB, 512>>>(Dgt);
    // 3: expand + adapt (split Hexp + outH)
    gather_adapt_kernel<<<NB * MAXF, 128>>>(H, Pgt, Egt, pw, pb, ew, eb, outH);
    // 4: split H for dp
    hsplit_kernel<<<NB * SEQ, 128>>>(H);

    // pitch predictor (conv 2,3; input Hexp)
    conv_mma_kernel<0><<<dim3(4, 256), 512, DSM_TOT>>>(0, 2, MAXF, 0, pp_b1, nullptr);
    conv_mma_kernel<1><<<dim3(4, 256), 512, DSM_TOT>>>(2, 3, MAXF, OFF_PP, pp_b2, pp_wl);
    // energy predictor (conv 4,5; input Hexp)
    conv_mma_kernel<0><<<dim3(4, 256), 512, DSM_TOT>>>(0, 4, MAXF, 0, ep_b1, nullptr);
    conv_mma_kernel<1><<<dim3(4, 256), 512, DSM_TOT>>>(3, 5, MAXF, OFF_EP, ep_b2, ep_wl);
    // duration predictor (conv 0,1; input H)
    conv_mma_kernel<0><<<dim3(4, 64), 512, DSM_TOT>>>(1, 0, SEQ, 0, dp_b1, nullptr);
    conv_mma_kernel<1><<<dim3(4, 64), 512, DSM_TOT>>>(4, 1, SEQ, OFF_DP, dp_b2, dp_wl);

    // final reduce
    reduce_all_kernel<<<(TOTROWS + 255) / 256, 256>>>(pp_bl, ep_bl, dp_bl, outP, outE, outD);
}

// round 12
// speedup vs baseline: 1.0903x; 1.0903x over previous
#include <cuda_runtime.h>
#include <cuda_bf16.h>
#include <cstdint>

#define NB     16
#define SEQ    512
#define DMODEL 512
#define MAXF   2048

// ---------------- scratch (static __device__ arrays: allowed) ----------------
__device__ __align__(128) float g_Hexp[NB * MAXF * DMODEL];          // fp32 Hexp (67MB)
__device__ __align__(128) float g_Y   [NB * MAXF * DMODEL];          // fp32 layer1 out (reused)
// Winograd-transformed weights: [conv][point][f][c], hi/lo bf16
__device__ __align__(128) __nv_bfloat16 g_Vhi[6 * 4 * 512 * 512];
__device__ __align__(128) __nv_bfloat16 g_Vlo[6 * 4 * 512 * 512];
#define TOTROWS (2 * NB * MAXF + NB * SEQ)   // pp | ep | dp output rows
__device__ float g_part[TOTROWS * 4];
__device__ int   g_idx [NB * MAXF];

// ================= baseline-ISA helpers (compute_103-safe) =================
__device__ __forceinline__ uint32_t smem_to_u32(const void* p) {
    uint32_t a;
    asm("{ .reg .u64 t; cvta.to.shared.u64 t, %1; cvt.u32.u64 %0, t; }" : "=r"(a) : "l"(p));
    return a;
}
__device__ __forceinline__ void cpasync16(uint32_t dst, const void* src) {
    asm volatile("cp.async.cg.shared.global [%0], [%1], 16;" :: "r"(dst), "l"(src));
}
#define CP_COMMIT() asm volatile("cp.async.commit_group;" ::: "memory")
#define CP_WAIT1()  asm volatile("cp.async.wait_group 1;"  ::: "memory")

__device__ __forceinline__ void ldmx4(uint32_t* r, uint32_t addr) {
    asm volatile("ldmatrix.sync.aligned.m8n8.x4.shared.b16 {%0,%1,%2,%3}, [%4];"
                 : "=r"(r[0]), "=r"(r[1]), "=r"(r[2]), "=r"(r[3]) : "r"(addr));
}
__device__ __forceinline__ void mma16816(float* d, const uint32_t* a, const uint32_t* b) {
    asm volatile("mma.sync.aligned.m16n8k16.row.col.f32.bf16.bf16.f32 "
                 "{%0,%1,%2,%3}, {%4,%5,%6,%7}, {%8,%9}, {%0,%1,%2,%3};"
                 : "+f"(d[0]), "+f"(d[1]), "+f"(d[2]), "+f"(d[3])
                 : "r"(a[0]), "r"(a[1]), "r"(a[2]), "r"(a[3]), "r"(b[0]), "r"(b[1]));
}
__device__ __forceinline__ uint32_t pack2bf(float a, float b) {
    __nv_bfloat162 t = __floats2bfloat162_rn(a, b);
    return *reinterpret_cast<uint32_t*>(&t);
}
// packed smem tile: 4 rows per 128B line (16ch bf16 = 32B/row = 2 x 16B segs), XOR swizzle
#define TADDR16(r, s) ((uint32_t)((((r) >> 2) * 128) + ((((((r) & 3) << 1) | (s)) ^ (((r) >> 2) & 7)) << 4)))

// ---------------- Winograd weight transform + hi/lo split ----------------
// w[f][c][k] -> V[conv][pt][f][c]:  V0=w0, V1=(w0+w1+w2)/2, V2=(w0-w1+w2)/2, V3=w2
__global__ void wtrans_wino_kernel(const float* __restrict__ w0p, const float* __restrict__ w1p,
                                   const float* __restrict__ w2p, const float* __restrict__ w3p,
                                   const float* __restrict__ w4p, const float* __restrict__ w5p) {
    int conv = blockIdx.x >> 9;
    int f    = blockIdx.x & 511;
    int c    = threadIdx.x;
    const float* w = conv == 0 ? w0p : conv == 1 ? w1p : conv == 2 ? w2p :
                     conv == 3 ? w3p : conv == 4 ? w4p : w5p;
    float w0 = w[(f * 512 + c) * 3 + 0];
    float w1 = w[(f * 512 + c) * 3 + 1];
    float w2 = w[(f * 512 + c) * 3 + 2];
    float V[4] = {w0, 0.5f * (w0 + w1 + w2), 0.5f * (w0 - w1 + w2), w2};
#pragma unroll
    for (int pt = 0; pt < 4; pt++) {
        long o = ((long)(conv * 4 + pt) * 512 + f) * 512 + c;
        __nv_bfloat16 h = __float2bfloat16(V[pt]);
        g_Vhi[o] = h;
        g_Vlo[o] = __float2bfloat16(V[pt] - __bfloat162float(h));
    }
}

// ---------------- duration cumsum + searchsorted ----------------
__global__ void duration_idx_kernel(const int* __restrict__ Dgt) {
    __shared__ int cs[512];
    int b = blockIdx.x, tid = threadIdx.x;
    int v = Dgt[b * 512 + tid];
    cs[tid] = v > 0 ? v : 0;
    __syncthreads();
    for (int off = 1; off < 512; off <<= 1) {
        int add = (tid >= off) ? cs[tid - off] : 0;
        __syncthreads();
        cs[tid] += add;
        __syncthreads();
    }
    int total = cs[511];
    int Tmax  = total < MAXF ? total : MAXF;
    for (int t = tid; t < MAXF; t += 512) {
        int r;
        if (t >= Tmax) {
            r = -1;
        } else {
            int lo = 0, hi = 511;
            while (lo < hi) {
                int mid = (lo + hi) >> 1;
                if (cs[mid] > t) hi = mid; else lo = mid + 1;
            }
            r = lo;
        }
        g_idx[b * MAXF + t] = r;
    }
}

// ---------------- gather H_exp (fp32) + fused variance adapt ----------------
__global__ void gather_adapt_kernel(const float* __restrict__ H,
                                    const float* __restrict__ P,
                                    const float* __restrict__ E,
                                    const float* __restrict__ pw,
                                    const float* __restrict__ pb,
                                    const float* __restrict__ ew,
                                    const float* __restrict__ eb,
                                    float* __restrict__ outH) {
    int bt  = blockIdx.x;
    int b   = bt >> 11;
    int idx = g_idx[bt];
    int d   = threadIdx.x * 4;
    float4 h = make_float4(0.f, 0.f, 0.f, 0.f);
    if (idx >= 0) h = *(const float4*)&H[((long)(b * 512 + idx)) * 512 + d];
    long xo = (long)bt * 512 + d;
    *(float4*)&g_Hexp[xo] = h;

    float p = P[bt], e = E[bt];
    float4 pw4 = *(const float4*)&pw[d];
    float4 pb4 = *(const float4*)&pb[d];
    float4 ew4 = *(const float4*)&ew[d];
    float4 eb4 = *(const float4*)&eb[d];
    float4 o;
    o.x = h.x + p * pw4.x + pb4.x + e * ew4.x + eb4.x;
    o.y = h.y + p * pw4.y + pb4.y + e * ew4.y + eb4.y;
    o.z = h.z + p * pw4.z + pb4.z + e * ew4.z + eb4.z;
    o.w = h.w + p * pw4.w + pb4.w + e * ew4.w + eb4.w;
    *(float4*)&outH[xo] = o;
}

// ---------------- Winograd F(2,3) conv1d, 3xBF16 compensated HMMA ----------------
// CTA: 64 output-pairs (=128 rows) x 128 filters, 512 threads (16 warps, 4M x 4N).
// 32 iterations of 16-ch chunks. Per iter per point (4 Winograd points):
// U_i[pair,c] x V_i[f,c] accumulated in fp32 (3-term bf16 hi/lo compensation).
// A: fp32 LDG (prefetched 1 iter ahead) -> transform -> split -> STS, double-buffered.
// B: pre-transformed bf16 weights via cp.async, ring-3. One barrier / iteration.
// Epilogue: y_{2t} = m0+m1+m2, y_{2t+1} = m1-m2-m3 (+bias, relu).
#define A_SLOT  4096                 // per point: hi 2048 | lo 2048
#define A_BUF   16384                // 4 points
#define B_BASE  32768                // after 2 A buffers
#define B_PT    8192                 // per point: hi 4096 | lo 4096
#define B_SLOT  32768                // 4 points
#define DSM_TOT (B_BASE + 3 * B_SLOT)   // 131072

template <int FUSED>
__global__ __launch_bounds__(512, 1)
void conv_wino_kernel(const float* __restrict__ X, int conv, int S, long rowOff,
                      const float* __restrict__ bias, const float* __restrict__ wl) {
    extern __shared__ char sm[];
    const uint32_t sb = smem_to_u32(sm);
    __shared__ float s_bias[128];
    __shared__ float s_wl[128];
    __shared__ float s_part[128][4];

    const int tid  = threadIdx.x;
    const int lane = tid & 31;
    const int wid  = tid >> 5;
    const int warpM = wid & 3, warpN = wid >> 2;
    const int rowW = warpM * 16;        // pair rows
    const int colW = warpN * 32;

    const int pairBase = blockIdx.y * 64;
    const int fBase    = blockIdx.x * 128;
    const int bb = (pairBase * 2) / S;
    const int s0 = pairBase * 2 - bb * S;
    const float* Xb = X + (long)bb * S * 512;

    if (tid < 128) {
        s_bias[tid] = bias[fBase + tid];
        if (FUSED) s_wl[tid] = wl[fBase + tid];
    }

    // ---- A loader setup: thread -> pair p, channel-group cg (2 ch) ----
    const int p  = tid >> 3;
    const int cg = tid & 7;
    const float* arow[4];
    bool av[4];
#pragma unroll
    for (int k = 0; k < 4; k++) {
        int s = s0 + 2 * p - 1 + k;
        av[k] = (s >= 0 && s < S);
        arow[k] = Xb + (long)(av[k] ? s : 0) * 512 + cg * 2;
    }
    const uint32_t aStsOff = TADDR16(p, cg >> 2) + (cg & 3) * 4;

    // ---- B staging: iteration it -> ring slot it%3, chunk c0 = it*16 ----
    auto stageB = [&](int it) {
        const int c0 = it << 4;
        const uint32_t bbuf = sb + B_BASE + (it % 3) * B_SLOT;
#pragma unroll
        for (int q = 0; q < 4; q++) {
            int idx = tid + q * 512;          // 0..2047
            int pt = idx >> 9, rem = idx & 511;
            int r = rem >> 2, hl = (rem >> 1) & 1, s = rem & 1;
            const __nv_bfloat16* src = (hl ? g_Vlo : g_Vhi) +
                (((long)(conv * 4 + pt) * 512 + fBase + r) * 512 + c0 + s * 8);
            cpasync16(bbuf + pt * B_PT + hl * 4096 + TADDR16(r, s), src);
        }
    };

    // ---- per-lane ldmatrix bases (R7-proven mapping) ----
    const int q = lane >> 3;
    const int am = rowW + ((q & 1) << 3) + (lane & 7);
    const int ac16b = q >> 1;
    int an[2];
#pragma unroll
    for (int np = 0; np < 2; np++) an[np] = colW + np * 16 + ((q >> 1) << 3) + (lane & 7);
    const int bc16b = q & 1;
    const uint32_t aOff = TADDR16(am, ac16b);
    uint32_t bOff[2];
#pragma unroll
    for (int np = 0; np < 2; np++) bOff[np] = TADDR16(an[np], bc16b);

    float acc[4][4][4];                 // [point][ntile][frag]
#pragma unroll
    for (int pt = 0; pt < 4; pt++)
#pragma unroll
        for (int nt = 0; nt < 4; nt++)
#pragma unroll
            for (int v = 0; v < 4; v++) acc[pt][nt][v] = 0.f;

    float2 d[4];
    auto loadA = [&](int it) {
        const int c0 = it << 4;
#pragma unroll
        for (int k = 0; k < 4; k++)
            d[k] = av[k] ? *(const float2*)(arow[k] + c0) : make_float2(0.f, 0.f);
    };
    auto stsA = [&](int it) {
        // Winograd input transform (fp32), then bf16 hi/lo split
        float U[4][2];
        U[0][0] = d[0].x - d[2].x;  U[0][1] = d[0].y - d[2].y;
        U[1][0] = d[1].x + d[2].x;  U[1][1] = d[1].y + d[2].y;
        U[2][0] = d[2].x - d[1].x;  U[2][1] = d[2].y - d[1].y;
        U[3][0] = d[1].x - d[3].x;  U[3][1] = d[1].y - d[3].y;
        char* abuf = sm + (it & 1) * A_BUF;
#pragma unroll
        for (int pt = 0; pt < 4; pt++) {
            __nv_bfloat16 h0 = __float2bfloat16(U[pt][0]);
            __nv_bfloat16 h1 = __float2bfloat16(U[pt][1]);
            float l0 = U[pt][0] - __bfloat162float(h0);
            float l1 = U[pt][1] - __bfloat162float(h1);
            __nv_bfloat162 hp = __halves2bfloat162(h0, h1);
            *(uint32_t*)(abuf + pt * A_SLOT + aStsOff)        = *(uint32_t*)&hp;
            *(uint32_t*)(abuf + pt * A_SLOT + 2048 + aStsOff) = pack2bf(l0, l1);
        }
    };

    // ---- pipeline prologue ----
    stageB(0); CP_COMMIT();
    stageB(1); CP_COMMIT();
    loadA(0);
    stsA(0);
    loadA(1);

    for (int it = 0; it < 32; it++) {
        CP_WAIT1();                       // B(it) complete
        __syncthreads();                  // A(it) STS visible
        const uint32_t aBuf = sb + (it & 1) * A_BUF;
        const uint32_t bBuf = sb + B_BASE + (it % 3) * B_SLOT;

#pragma unroll
        for (int pt = 0; pt < 4; pt++) {
            uint32_t ah[4], al[4];
            ldmx4(ah, aBuf + pt * A_SLOT + aOff);
            ldmx4(al, aBuf + pt * A_SLOT + 2048 + aOff);
            uint32_t bh[4][2], bl[4][2];
#pragma unroll
            for (int np = 0; np < 2; np++) {
                uint32_t t[4];
                ldmx4(t, bBuf + pt * B_PT + bOff[np]);
                bh[2 * np][0] = t[0]; bh[2 * np][1] = t[1];
                bh[2 * np + 1][0] = t[2]; bh[2 * np + 1][1] = t[3];
                ldmx4(t, bBuf + pt * B_PT + 4096 + bOff[np]);
                bl[2 * np][0] = t[0]; bl[2 * np][1] = t[1];
                bl[2 * np + 1][0] = t[2]; bl[2 * np + 1][1] = t[3];
            }
#pragma unroll
            for (int nt = 0; nt < 4; nt++) mma16816(acc[pt][nt], ah, bh[nt]);
#pragma unroll
            for (int nt = 0; nt < 4; nt++) mma16816(acc[pt][nt], ah, bl[nt]);
#pragma unroll
            for (int nt = 0; nt < 4; nt++) mma16816(acc[pt][nt], al, bh[nt]);
        }

        if (it + 1 < 32) stsA(it + 1);                  // write other A buffer
        if (it + 2 < 32) { loadA(it + 2); stageB(it + 2); }
        CP_COMMIT();
    }

    // ---------------- epilogue: output transform + bias + relu ----------------
    const int tq = lane >> 2;
    const int tr = lane & 3;
    if (FUSED == 0) {
#pragma unroll
        for (int nt = 0; nt < 4; nt++) {
            const int cl = colW + nt * 8 + 2 * tr;
            const float b0 = s_bias[cl], b1 = s_bias[cl + 1];
#pragma unroll
            for (int h = 0; h < 2; h++) {
                const long P = pairBase + rowW + tq + 8 * h;
                const int v0 = 2 * h, v1 = 2 * h + 1;
                float m0a = acc[0][nt][v0], m1a = acc[1][nt][v0],
                      m2a = acc[2][nt][v0], m3a = acc[3][nt][v0];
                float m0b = acc[0][nt][v1], m1b = acc[1][nt][v1],
                      m2b = acc[2][nt][v1], m3b = acc[3][nt][v1];
                float y0a = fmaxf(m0a + m1a + m2a + b0, 0.f);
                float y0b = fmaxf(m0b + m1b + m2b + b1, 0.f);
                float y1a = fmaxf(m1a - m2a - m3a + b0, 0.f);
                float y1b = fmaxf(m1b - m2b - m3b + b1, 0.f);
                *(float2*)&g_Y[(2 * P)     * 512 + fBase + cl] = make_float2(y0a, y0b);
                *(float2*)&g_Y[(2 * P + 1) * 512 + fBase + cl] = make_float2(y1a, y1b);
            }
        }
    } else {
        float s00 = 0.f, s10 = 0.f, s01 = 0.f, s11 = 0.f;   // s{y0/y1}{h}
#pragma unroll
        for (int nt = 0; nt < 4; nt++) {
            const int cl = colW + nt * 8 + 2 * tr;
            const float b0 = s_bias[cl], b1 = s_bias[cl + 1];
            const float w0 = s_wl[cl], w1 = s_wl[cl + 1];
#pragma unroll
            for (int h = 0; h < 2; h++) {
                const int v0 = 2 * h, v1 = 2 * h + 1;
                float m0a = acc[0][nt][v0], m1a = acc[1][nt][v0],
                      m2a = acc[2][nt][v0], m3a = acc[3][nt][v0];
                float m0b = acc[0][nt][v1], m1b = acc[1][nt][v1],
                      m2b = acc[2][nt][v1], m3b = acc[3][nt][v1];
                float sy0 = fmaxf(m0a + m1a + m2a + b0, 0.f) * w0
                          + fmaxf(m0b + m1b + m2b + b1, 0.f) * w1;
                float sy1 = fmaxf(m1a - m2a - m3a + b0, 0.f) * w0
                          + fmaxf(m1b - m2b - m3b + b1, 0.f) * w1;
                if (h == 0) { s00 += sy0; s10 += sy1; }
                else        { s01 += sy0; s11 += sy1; }
            }
        }
        s00 += __shfl_xor_sync(0xFFFFFFFF, s00, 1);
        s00 += __shfl_xor_sync(0xFFFFFFFF, s00, 2);
        s10 += __shfl_xor_sync(0xFFFFFFFF, s10, 1);
        s10 += __shfl_xor_sync(0xFFFFFFFF, s10, 2);
        s01 += __shfl_xor_sync(0xFFFFFFFF, s01, 1);
        s01 += __shfl_xor_sync(0xFFFFFFFF, s01, 2);
        s11 += __shfl_xor_sync(0xFFFFFFFF, s11, 1);
        s11 += __shfl_xor_sync(0xFFFFFFFF, s11, 2);
        if (tr == 0) {
            int lr0 = 2 * (rowW + tq);
            int lr1 = 2 * (rowW + tq + 8);
            s_part[lr0][warpN]     = s00;
            s_part[lr0 + 1][warpN] = s10;
            s_part[lr1][warpN]     = s01;
            s_part[lr1 + 1][warpN] = s11;
        }
        __syncthreads();
        if (tid < 128)
            g_part[(rowOff + (long)blockIdx.y * 128 + tid) * 4 + blockIdx.x] =
                (s_part[tid][0] + s_part[tid][1]) + (s_part[tid][2] + s_part[tid][3]);
    }
}

// ---------------- merged final reduce: pp | ep | dp ----------------
__global__ void reduce_all_kernel(const float* __restrict__ pp_bl,
                                  const float* __restrict__ ep_bl,
                                  const float* __restrict__ dp_bl,
                                  float* __restrict__ outP,
                                  float* __restrict__ outE,
                                  float* __restrict__ outD) {
    int i = blockIdx.x * 256 + threadIdx.x;
    if (i >= TOTROWS) return;
    float s = (g_part[(long)i * 4 + 0] + g_part[(long)i * 4 + 1]) +
              (g_part[(long)i * 4 + 2] + g_part[(long)i * 4 + 3]);
    const int nPP = NB * MAXF, nPE = 2 * NB * MAXF;
    if (i < nPP)       outP[i]        = pp_bl[0] + s;
    else if (i < nPE)  outE[i - nPP]  = ep_bl[0] + s;
    else               outD[i - nPE]  = dp_bl[0] + s;
}

// ---------------- launch ----------------
extern "C" void kernel_launch(void* const* d_in, const int* in_sizes, int n_in,
                              void* d_out, int out_size) {
    const float* H     = (const float*)d_in[0];
    const int*   Dgt   = (const int*)  d_in[1];
    const float* Pgt   = (const float*)d_in[2];
    const float* Egt   = (const float*)d_in[3];
    const float* dp_w1 = (const float*)d_in[4];
    const float* dp_b1 = (const float*)d_in[5];
    const float* dp_w2 = (const float*)d_in[6];
    const float* dp_b2 = (const float*)d_in[7];
    const float* dp_wl = (const float*)d_in[8];
    const float* dp_bl = (const float*)d_in[9];
    const float* pp_w1 = (const float*)d_in[10];
    const float* pp_b1 = (const float*)d_in[11];
    const float* pp_w2 = (const float*)d_in[12];
    const float* pp_b2 = (const float*)d_in[13];
    const float* pp_wl = (const float*)d_in[14];
    const float* pp_bl = (const float*)d_in[15];
    const float* ep_w1 = (const float*)d_in[16];
    const float* ep_b1 = (const float*)d_in[17];
    const float* ep_w2 = (const float*)d_in[18];
    const float* ep_b2 = (const float*)d_in[19];
    const float* ep_wl = (const float*)d_in[20];
    const float* ep_bl = (const float*)d_in[21];
    const float* pw    = (const float*)d_in[22];
    const float* pb    = (const float*)d_in[23];
    const float* ew    = (const float*)d_in[24];
    const float* eb    = (const float*)d_in[25];

    float* out  = (float*)d_out;
    float* outH = out;                                   // (16,2048,512)
    float* outD = out + (long)NB * MAXF * DMODEL;        // (16,512)
    float* outP = outD + NB * SEQ;                       // (16,2048)
    float* outE = outP + NB * MAXF;                      // (16,2048)

    cudaFuncSetAttribute(conv_wino_kernel<0>, cudaFuncAttributeMaxDynamicSharedMemorySize, DSM_TOT);
    cudaFuncSetAttribute(conv_wino_kernel<1>, cudaFuncAttributeMaxDynamicSharedMemorySize, DSM_TOT);

    const long OFF_PP = 0, OFF_EP = (long)NB * MAXF, OFF_DP = 2L * NB * MAXF;
    float* gHexp;  cudaGetSymbolAddress((void**)&gHexp, g_Hexp);
    float* gY;     cudaGetSymbolAddress((void**)&gY, g_Y);

    // 1: Winograd weight transforms (all 6 convs)
    wtrans_wino_kernel<<<6 * 512, 512>>>(dp_w1, dp_w2, pp_w1, pp_w2, ep_w1, ep_w2);
    // 2: duration indices
    duration_idx_kernel<<<NB, 512>>>(Dgt);
    // 3: expand + adapt (fp32 Hexp + outH)
    gather_adapt_kernel<<<NB * MAXF, 128>>>(H, Pgt, Egt, pw, pb, ew, eb, outH);

    // pitch predictor (conv 2,3)
    conv_wino_kernel<0><<<dim3(4, 256), 512, DSM_TOT>>>(gHexp, 2, MAXF, 0, pp_b1, nullptr);
    conv_wino_kernel<1><<<dim3(4, 256), 512, DSM_TOT>>>(gY,    3, MAXF, OFF_PP, pp_b2, pp_wl);
    // energy predictor (conv 4,5) — launch #6 is the ncu-profiled conv
    conv_wino_kernel<0><<<dim3(4, 256), 512, DSM_TOT>>>(gHexp, 4, MAXF, 0, ep_b1, nullptr);
    conv_wino_kernel<1><<<dim3(4, 256), 512, DSM_TOT>>>(gY,    5, MAXF, OFF_EP, ep_b2, ep_wl);
    // duration predictor (conv 0,1; input H fp32 directly)
    conv_wino_kernel<0><<<dim3(4, 64), 512, DSM_TOT>>>(H,  0, SEQ, 0, dp_b1, nullptr);
    conv_wino_kernel<1><<<dim3(4, 64), 512, DSM_TOT>>>(gY, 1, SEQ, OFF_DP, dp_b2, dp_wl);

    // final reduce
    reduce_all_kernel<<<(TOTROWS + 255) / 256, 256>>>(pp_bl, ep_bl, dp_bl, outP, outE, outD);
}